// round 1
// baseline (speedup 1.0000x reference)
#include <cuda_runtime.h>
#include <cuda_bf16.h>
#include <cstdint>

// NLTKHierarchicalSoftmax: B=4096, NHID=512, BR=32, DEPTH=3
// inputs: d_in[0] float32 [B,512]
// labels: d_in[1] int32   [B]
// W:      d_in[2] float32 [1057,512,32]
// out:    float32 [B]
//
// Level k: node = LEVEL_OFFSET[k] + lab/NODE_DIV[k]; step = (lab/STEP_DIV[k])%32
//   LEVEL_OFFSET = {0, 1, 33}; NODE_DIV = {32768, 1024, 32}; STEP_DIV = {1024, 32, 1}

#define NHID 512
#define BR 32
#define WNODE_ELEMS (NHID * BR)  // 16384

__global__ void __launch_bounds__(256) hs_warp_per_sample(
    const float* __restrict__ x,
    const int* __restrict__ labels,
    const float* __restrict__ W,
    float* __restrict__ out,
    int B)
{
    const unsigned FULL = 0xffffffffu;
    int gwarp = (blockIdx.x * blockDim.x + threadIdx.x) >> 5;
    int lane = threadIdx.x & 31;
    if (gwarp >= B) return;

    const int b = gwarp;
    const int lab = labels[b];
    const float* __restrict__ xb = x + (size_t)b * NHID;

    // per-level node and step indices
    int node[3];
    int step[3];
    node[0] = 0;                 step[0] = (lab >> 10) & 31;
    node[1] = 1 + (lab >> 10);   step[1] = (lab >> 5) & 31;
    node[2] = 33 + (lab >> 5);   step[2] = lab & 31;

    float prod = 1.0f;

    #pragma unroll 1
    for (int k = 0; k < 3; k++) {
        const float* __restrict__ Wn = W + (size_t)node[k] * WNODE_ELEMS;
        float acc = 0.0f;

        // 16 chunks of 32 h-values each. Per chunk: 32 independent coalesced
        // W loads (MLP=32) + 1 coalesced x load, then shfl-broadcast FMAs.
        #pragma unroll 1
        for (int c = 0; c < NHID / 32; c++) {
            const int h0 = c * 32;
            float w[32];
            #pragma unroll
            for (int j = 0; j < 32; j++) {
                w[j] = Wn[(h0 + j) * BR + lane];
            }
            float xr = xb[h0 + lane];
            #pragma unroll
            for (int j = 0; j < 32; j++) {
                acc = fmaf(__shfl_sync(FULL, xr, j), w[j], acc);
            }
        }

        // warp softmax over 32 logits (lane = column)
        float m = acc;
        #pragma unroll
        for (int o = 16; o > 0; o >>= 1)
            m = fmaxf(m, __shfl_xor_sync(FULL, m, o));
        float e = __expf(acc - m);
        float s = e;
        #pragma unroll
        for (int o = 16; o > 0; o >>= 1)
            s += __shfl_xor_sync(FULL, s, o);
        // all lanes hold full sum s; fetch numerator at the step lane
        float estep = __shfl_sync(FULL, e, step[k]);
        prod *= estep / s;
    }

    if (lane == 0) out[b] = prod;
}

extern "C" void kernel_launch(void* const* d_in, const int* in_sizes, int n_in,
                              void* d_out, int out_size)
{
    const float* x      = (const float*)d_in[0];
    const int*   labels = (const int*)d_in[1];
    const float* W      = (const float*)d_in[2];
    float* out = (float*)d_out;

    int B = in_sizes[1];  // number of labels == number of samples

    const int threads = 256;                 // 8 warps per CTA
    int warps_needed = B;
    int blocks = (warps_needed * 32 + threads - 1) / threads;

    hs_warp_per_sample<<<blocks, threads>>>(x, labels, W, out, B);
}

// round 2
// speedup vs baseline: 1.2533x; 1.2533x over previous
#include <cuda_runtime.h>
#include <cuda_bf16.h>
#include <cstdint>

// NLTKHierarchicalSoftmax: B=4096, NHID=512, BR=32, DEPTH=3
// Grouped (label-sorted) implementation:
//   counting sort by (lab>>5) -> 1024 buckets
//   level 0: node 0 for everyone; level 1: node 1+(lab>>10) (= bucket>>5);
//   level 2: node 33+(lab>>5) (= bucket). Sorted order groups all levels.
// Work kernel: warp processes a run of <=8 samples sharing one node.
//   lane = output column. W chunk (32 h x 32 cols) held in 32 regs per lane,
//   x broadcast across lanes via __shfl -> W read once per <=8 samples.

#define FULL 0xffffffffu
#define NHID 512
#define BR 32
#define NB2 1024
#define BTOT 4096
#define WNODE (NHID*BR)

__device__ int g_counts[NB2];
__device__ int g_off[NB2 + 1];
__device__ int g_cursor[NB2];
__device__ int g_sorted[BTOT];
__device__ float g_p[3 * BTOT];

__global__ void k_init()
{
    int i = blockIdx.x * blockDim.x + threadIdx.x;
    if (i < NB2) g_counts[i] = 0;
}

__global__ void k_hist(const int* __restrict__ labels, int B)
{
    int i = blockIdx.x * blockDim.x + threadIdx.x;
    if (i < B) atomicAdd(&g_counts[labels[i] >> 5], 1);
}

__global__ void k_scan()
{
    __shared__ int sm[NB2];
    int i = threadIdx.x;
    int v = g_counts[i];
    sm[i] = v;
    __syncthreads();
    #pragma unroll
    for (int off = 1; off < NB2; off <<= 1) {
        int t = (i >= off) ? sm[i - off] : 0;
        __syncthreads();
        sm[i] += t;
        __syncthreads();
    }
    int excl = sm[i] - v;
    g_off[i] = excl;
    g_cursor[i] = excl;
    if (i == NB2 - 1) g_off[NB2] = sm[i];
}

__global__ void k_scatter(const int* __restrict__ labels, int B)
{
    int i = blockIdx.x * blockDim.x + threadIdx.x;
    if (i < B) {
        int key = labels[i] >> 5;
        int pos = atomicAdd(&g_cursor[key], 1);
        g_sorted[pos] = i;
    }
}

// Compute logits+softmax for up to TS samples sharing node Wn.
// lane = column. msk selects which sample slots get an output.
template<int TS>
__device__ __forceinline__ void process_run(
    const float* __restrict__ x, const float* __restrict__ Wn,
    const int* bs, unsigned msk, const int* step,
    int G, int lane, float* __restrict__ pout)
{
    float acc[TS];
    #pragma unroll
    for (int s = 0; s < TS; s++) acc[s] = 0.f;

    #pragma unroll 1
    for (int c = 0; c < NHID / 32; c++) {
        // W chunk: 32 h-rows, this lane's column. 32 coalesced LDG.
        float wreg[32];
        #pragma unroll
        for (int j = 0; j < 32; j++)
            wreg[j] = __ldg(Wn + (c * 32 + j) * BR + lane);

        // x chunk per sample: lane holds h = c*32+lane. Coalesced 128B row.
        float xs[TS];
        #pragma unroll
        for (int s = 0; s < TS; s++)
            xs[s] = (s < G) ? __ldg(x + (size_t)bs[s] * NHID + c * 32 + lane)
                            : 0.f;

        #pragma unroll
        for (int j = 0; j < 32; j++) {
            #pragma unroll
            for (int s = 0; s < TS; s++)
                acc[s] = fmaf(wreg[j], __shfl_sync(FULL, xs[s], j), acc[s]);
        }
    }

    // per-sample warp softmax over the 32 columns
    #pragma unroll
    for (int s = 0; s < TS; s++) {
        if (msk & (1u << s)) {
            float m = acc[s];
            #pragma unroll
            for (int o = 16; o > 0; o >>= 1)
                m = fmaxf(m, __shfl_xor_sync(FULL, m, o));
            float e = __expf(acc[s] - m);
            float sum = e;
            #pragma unroll
            for (int o = 16; o > 0; o >>= 1)
                sum += __shfl_xor_sync(FULL, sum, o);
            float est = __shfl_sync(FULL, e, step[s]);
            if (lane == 0) pout[bs[s]] = est / sum;
        }
    }
}

__global__ void __launch_bounds__(256, 2) k_work(
    const float* __restrict__ x, const int* __restrict__ labels,
    const float* __restrict__ W)
{
    int gw = (blockIdx.x * blockDim.x + threadIdx.x) >> 5;
    int lane = threadIdx.x & 31;

    if (gw < 1024) {
        // levels 0 and 1: tiles of 8 consecutive sorted samples
        int level = gw >> 9;      // 0 or 1
        int tile = gw & 511;
        int s0 = tile * 8;

        int bs[8], step[8], node[8];
        #pragma unroll
        for (int s = 0; s < 8; s++) {
            bs[s] = __ldg(&g_sorted[s0 + s]);         // uniform load
            int lab = __ldg(&labels[bs[s]]);          // uniform load
            if (level == 0) { node[s] = 0;                step[s] = (lab >> 10) & 31; }
            else            { node[s] = 1 + (lab >> 10);  step[s] = (lab >> 5) & 31; }
        }

        // runs of equal node (level 0: always one run; level 1: rarely two)
        unsigned rem = 0xffu;
        while (rem) {
            int src = __ffs(rem) - 1;
            int n = node[src];                         // uniform
            unsigned msk = 0;
            #pragma unroll
            for (int s = 0; s < 8; s++)
                if (node[s] == n) msk |= 1u << s;
            process_run<8>(x, W + (size_t)n * WNODE, bs, msk, step, 8, lane,
                           g_p + level * BTOT);
            rem &= ~msk;
        }
    } else if (gw < 1024 + NB2) {
        // level 2: one warp per bucket (node 33 + bucket)
        int w = gw - 1024;
        int beg = __ldg(&g_off[w]);
        int end = __ldg(&g_off[w + 1]);
        const float* Wn = W + (size_t)(33 + w) * WNODE;

        for (int t = beg; t < end; t += 8) {
            int G = min(8, end - t);
            int bs[8], step[8];
            #pragma unroll
            for (int s = 0; s < 8; s++) {
                int b = (s < G) ? __ldg(&g_sorted[t + s]) : 0;
                bs[s] = b;
                int lab = (s < G) ? __ldg(&labels[b]) : 0;
                step[s] = lab & 31;
            }
            unsigned msk = (G >= 8) ? 0xffu : ((1u << G) - 1u);
            if (G <= 4)
                process_run<4>(x, Wn, bs, msk, step, G, lane, g_p + 2 * BTOT);
            else
                process_run<8>(x, Wn, bs, msk, step, G, lane, g_p + 2 * BTOT);
        }
    }
}

__global__ void k_final(float* __restrict__ out, int B)
{
    int i = blockIdx.x * blockDim.x + threadIdx.x;
    if (i < B) out[i] = g_p[i] * g_p[BTOT + i] * g_p[2 * BTOT + i];
}

extern "C" void kernel_launch(void* const* d_in, const int* in_sizes, int n_in,
                              void* d_out, int out_size)
{
    const float* x      = (const float*)d_in[0];
    const int*   labels = (const int*)d_in[1];
    const float* W      = (const float*)d_in[2];
    float* out = (float*)d_out;

    int B = in_sizes[1];  // 4096

    k_init<<<(NB2 + 255) / 256, 256>>>();
    k_hist<<<(B + 255) / 256, 256>>>(labels, B);
    k_scan<<<1, NB2>>>();
    k_scatter<<<(B + 255) / 256, 256>>>(labels, B);

    // 2048 warps: 1024 for levels 0/1 tiles, 1024 for level-2 buckets
    int warps = 1024 + NB2;
    int threads = 256;
    int blocks = (warps * 32 + threads - 1) / threads;
    k_work<<<blocks, threads>>>(x, labels, W);

    k_final<<<(B + 255) / 256, 256>>>(out, B);
}